// round 2
// baseline (speedup 1.0000x reference)
#include <cuda_runtime.h>
#include <cuda_bf16.h>
#include <cstdint>

#define Nn   8
#define Cch  256
#define HWX  4096
#define EPSF 1e-6f
#define LOG2E 1.44269504088896340736f

// ---------------- device scratch (static: allocation-free) ----------------
__device__ float g_mu[Cch];
__device__ float g_invnx[Nn * HWX];
__device__ float g_invny[Nn * HWX];
__device__ float g_Xn[(size_t)Nn * HWX * Cch];   // [n][hw][c]  (K-contiguous)
__device__ float g_Yn[(size_t)Nn * HWX * Cch];
__device__ float g_cosM[(size_t)Nn * HWX * HWX]; // 512 MB cosine matrix
__device__ float g_rA[Nn * HWX];                 // per-row i:  A_i = 2/dmp
__device__ float g_rB[Nn * HWX];                 // per-row i:  B_i = 2 - 2/dmp - ln(S)
__device__ unsigned g_cmax[Nn * HWX];            // column-max keys (order-preserving bits)

// ---------------- helpers ----------------
// FMA-pipe exp2 (avoids MUFU bottleneck). Valid for x >= -80; rel err ~2e-7.
__device__ __forceinline__ float fexp2(float x) {
    x = fmaxf(x, -80.0f);
    float fx = x + 12582912.0f;              // round-to-nearest-int trick (1.5*2^23)
    float r  = x - (fx - 12582912.0f);       // r in [-0.5, 0.5]
    int   n  = __float_as_int(fx) - 0x4B400000;
    float p  = 0.69314718056f + r * (0.2402265069f + r * (0.0555041087f +
               r * (0.00961812911f + r * (0.00133335581f + r * 0.000154035304f))));
    p = 1.0f + r * p;                        // 2^r
    return __int_as_float(__float_as_int(p) + (n << 23));
}

// Order-preserving float->uint key (handles negatives) for atomicMax.
__device__ __forceinline__ unsigned fkey(float f) {
    unsigned u = __float_as_uint(f);
    return (u & 0x80000000u) ? ~u : (u | 0x80000000u);
}
__device__ __forceinline__ float funkey(unsigned k) {
    return __uint_as_float((k & 0x80000000u) ? (k & 0x7fffffffu) : ~k);
}

// ---------------- kernels ----------------
__global__ void k_init() {
    int idx = blockIdx.x * 256 + threadIdx.x;
    if (idx < Nn * HWX) g_cmax[idx] = 0u;    // key(0) is below every finite key
}

// per-channel mean of y over (N,H,W)
__global__ void k_mu(const float* __restrict__ y) {
    int c = blockIdx.x, tid = threadIdx.x;
    float s = 0.f;
    for (int n = 0; n < Nn; n++) {
        const float* p = y + ((size_t)n * Cch + c) * HWX;
        for (int t = tid; t < HWX; t += 256) s += p[t];
    }
    __shared__ float red[256];
    red[tid] = s; __syncthreads();
    for (int o = 128; o > 0; o >>= 1) { if (tid < o) red[tid] += red[tid + o]; __syncthreads(); }
    if (tid == 0) g_mu[c] = red[0] * (1.0f / (Nn * HWX));
}

// per-(n,hw) channel L2 norms of x-mu, y-mu
__global__ void k_norm(const float* __restrict__ x, const float* __restrict__ y) {
    int n = blockIdx.y;
    int i = blockIdx.x * 256 + threadIdx.x;
    __shared__ float smu[Cch];
    smu[threadIdx.x] = g_mu[threadIdx.x];    // blockDim == Cch == 256
    __syncthreads();
    const float* xb = x + (size_t)n * Cch * HWX + i;
    const float* yb = y + (size_t)n * Cch * HWX + i;
    float sx = 0.f, sy = 0.f;
#pragma unroll 4
    for (int c = 0; c < Cch; c++) {
        float m  = smu[c];
        float xv = xb[(size_t)c * HWX] - m;
        float yv = yb[(size_t)c * HWX] - m;
        sx = fmaf(xv, xv, sx);
        sy = fmaf(yv, yv, sy);
    }
    g_invnx[n * HWX + i] = rsqrtf(sx);
    g_invny[n * HWX + i] = rsqrtf(sy);
}

// transpose (n,c,hw) -> (n,hw,c) with mean-subtract + normalize
__global__ void k_trans(const float* __restrict__ x, const float* __restrict__ y) {
    int n = blockIdx.z, c0 = blockIdx.y * 32, h0 = blockIdx.x * 32;
    __shared__ float tx[32][33], tyv[32][33];
    for (int r = threadIdx.y; r < 32; r += 8) {
        int c = c0 + r, h = h0 + threadIdx.x;
        float m = g_mu[c];
        size_t off = ((size_t)n * Cch + c) * HWX + h;
        tx[r][threadIdx.x]  = x[off] - m;
        tyv[r][threadIdx.x] = y[off] - m;
    }
    __syncthreads();
    for (int r = threadIdx.y; r < 32; r += 8) {
        int h = h0 + r, c = c0 + threadIdx.x;
        size_t off = ((size_t)n * HWX + h) * Cch + c;
        g_Xn[off] = tx[threadIdx.x][r]  * g_invnx[n * HWX + h];
        g_Yn[off] = tyv[threadIdx.x][r] * g_invny[n * HWX + h];
    }
}

// batched fp32 GEMM: cos[n] = Xn (4096x256) * Yn^T (256x4096)
// 128x128 block tile, BK=8, 256 threads, 8x8 per thread.
__global__ void __launch_bounds__(256) k_gemm() {
    int n = blockIdx.z;
    const float* A = g_Xn + (size_t)n * HWX * Cch;
    const float* B = g_Yn + (size_t)n * HWX * Cch;
    float* Co = g_cosM + (size_t)n * HWX * HWX;
    int i0 = blockIdx.y * 128, j0 = blockIdx.x * 128;

    __shared__ float As[8][128];
    __shared__ float Bs[8][128];

    int tid  = threadIdx.x;
    int lrow = tid >> 1;
    int lk   = (tid & 1) << 2;
    int tx   = tid & 15, ty = tid >> 4;

    const float* Ap = A + (size_t)(i0 + lrow) * Cch + lk;
    const float* Bp = B + (size_t)(j0 + lrow) * Cch + lk;

    float acc[8][8];
#pragma unroll
    for (int r = 0; r < 8; r++)
#pragma unroll
        for (int s = 0; s < 8; s++) acc[r][s] = 0.f;

    for (int k0 = 0; k0 < Cch; k0 += 8) {
        float4 av = *(const float4*)(Ap + k0);
        float4 bv = *(const float4*)(Bp + k0);
        As[lk + 0][lrow] = av.x; As[lk + 1][lrow] = av.y;
        As[lk + 2][lrow] = av.z; As[lk + 3][lrow] = av.w;
        Bs[lk + 0][lrow] = bv.x; Bs[lk + 1][lrow] = bv.y;
        Bs[lk + 2][lrow] = bv.z; Bs[lk + 3][lrow] = bv.w;
        __syncthreads();
#pragma unroll
        for (int k = 0; k < 8; k++) {
            float ar[8], br[8];
            *(float4*)&ar[0] = *(const float4*)&As[k][ty * 8];
            *(float4*)&ar[4] = *(const float4*)&As[k][ty * 8 + 4];
            *(float4*)&br[0] = *(const float4*)&Bs[k][tx * 8];
            *(float4*)&br[4] = *(const float4*)&Bs[k][tx * 8 + 4];
#pragma unroll
            for (int r = 0; r < 8; r++)
#pragma unroll
                for (int s = 0; s < 8; s++)
                    acc[r][s] = fmaf(ar[r], br[s], acc[r][s]);
        }
        __syncthreads();
    }
#pragma unroll
    for (int r = 0; r < 8; r++) {
        float* cp = Co + (size_t)(i0 + ty * 8 + r) * HWX + j0 + tx * 8;
        *(float4*)cp       = make_float4(acc[r][0], acc[r][1], acc[r][2], acc[r][3]);
        *(float4*)(cp + 4) = make_float4(acc[r][4], acc[r][5], acc[r][6], acc[r][7]);
    }
}

// per-row: dmin' = 1 - max_j cos + eps ; S = sum_j exp(2 - 2(1-cos)/dmin')
// store A_i = 2/dmp, B_i = 2 - 2/dmp - ln(S)  (log-domain for the column pass)
__global__ void k_row() {
    int n = blockIdx.y, i = blockIdx.x, tid = threadIdx.x;
    const float* row = g_cosM + ((size_t)n * HWX + i) * HWX;
    __shared__ float sr[HWX];          // 16 KB row cache
    __shared__ float red[256];

    float mx = -1e30f;
    for (int j = tid; j < HWX; j += 256) { float v = row[j]; sr[j] = v; mx = fmaxf(mx, v); }
    red[tid] = mx; __syncthreads();
    for (int o = 128; o > 0; o >>= 1) { if (tid < o) red[tid] = fmaxf(red[tid], red[tid + o]); __syncthreads(); }
    float dmp = 1.0f - red[0] + EPSF;
    __syncthreads();

    float inv = 2.0f / dmp;
    float a2  = inv * LOG2E;
    float b2  = (2.0f - inv) * LOG2E;
    float s = 0.f;
    for (int j = tid; j < HWX; j += 256) s += fexp2(fmaf(a2, sr[j], b2));
    red[tid] = s; __syncthreads();
    for (int o = 128; o > 0; o >>= 1) { if (tid < o) red[tid] += red[tid + o]; __syncthreads(); }
    if (tid == 0) {
        g_rA[n * HWX + i] = inv;
        g_rB[n * HWX + i] = (2.0f - inv) - logf(red[0]);
    }
}

// per-column: max_i (A_i*cos_ij + B_i)   (= log of max_i w_ij/S_i, monotone)
__global__ void __launch_bounds__(128) k_colmax() {
    int n = blockIdx.z;
    int j = blockIdx.x * 128 + threadIdx.x;
    int i0 = blockIdx.y * 128;
    const float* base = g_cosM + ((size_t)n * HWX + i0) * HWX + j;
    float best = -1e30f;
#pragma unroll 4
    for (int ii = 0; ii < 128; ii++) {
        float cv = base[(size_t)ii * HWX];
        float t  = fmaf(g_rA[n * HWX + i0 + ii], cv, g_rB[n * HWX + i0 + ii]);
        best = fmaxf(best, t);
    }
    atomicMax(&g_cmax[n * HWX + j], fkey(best));
}

// loss = mean_n( -log( mean_j exp(colmax[n][j]) + eps ) )
__global__ void k_final(float* __restrict__ out) {
    int tid = threadIdx.x;
    __shared__ float red[256];
    float acc = 0.f;
    for (int n = 0; n < Nn; n++) {
        float s = 0.f;
        for (int j = tid; j < HWX; j += 256) s += expf(funkey(g_cmax[n * HWX + j]));
        red[tid] = s; __syncthreads();
        for (int o = 128; o > 0; o >>= 1) { if (tid < o) red[tid] += red[tid + o]; __syncthreads(); }
        if (tid == 0) {
            float ccx = red[0] * (1.0f / HWX);
            acc += -logf(ccx + EPSF);
        }
        __syncthreads();
    }
    if (tid == 0) out[0] = acc * (1.0f / Nn);
}

// ---------------- launcher ----------------
extern "C" void kernel_launch(void* const* d_in, const int* in_sizes, int n_in,
                              void* d_out, int out_size) {
    const float* x = (const float*)d_in[0];
    const float* y = (const float*)d_in[1];
    float* out = (float*)d_out;

    k_init<<<(Nn * HWX + 255) / 256, 256>>>();
    k_mu<<<Cch, 256>>>(y);
    k_norm<<<dim3(HWX / 256, Nn), 256>>>(x, y);
    k_trans<<<dim3(HWX / 32, Cch / 32, Nn), dim3(32, 8)>>>(x, y);
    k_gemm<<<dim3(HWX / 128, HWX / 128, Nn), 256>>>();
    k_row<<<dim3(HWX, Nn), 256>>>();
    k_colmax<<<dim3(HWX / 128, HWX / 128, Nn), 128>>>();
    k_final<<<1, 256>>>(out);
}

// round 7
// speedup vs baseline: 1.4936x; 1.4936x over previous
#include <cuda_runtime.h>
#include <cuda_bf16.h>
#include <cstdint>

#define Nn   8
#define Cch  256
#define HWX  4096
#define EPSF 1e-6f
#define LOG2E 1.44269504088896340736f

// GEMM tiling
#define BM 128
#define BN 128
#define BK 32
#define NCHUNK (Cch / BK)   // 8

// smem layout (bytes): row stride 80 (64B data + 16B pad) -> conflict-free ldmatrix
#define ROWB   80
#define OFF_AHI 0
#define OFF_ALO (128 * ROWB)
#define OFF_BHI (2 * 128 * ROWB)
#define OFF_BLO (3 * 128 * ROWB)
#define STAGE   (4 * 128 * ROWB)       // 40960
#define SMEM_DYN (2 * STAGE)           // 81920

// ---------------- device scratch ----------------
__device__ float g_mu[Cch];
__device__ float g_invnx[Nn * HWX];
__device__ float g_invny[Nn * HWX];
__device__ __nv_bfloat16 g_Xhi[(size_t)Nn * HWX * Cch];  // [n][hw][c] K-major
__device__ __nv_bfloat16 g_Xlo[(size_t)Nn * HWX * Cch];
__device__ __nv_bfloat16 g_Yhi[(size_t)Nn * HWX * Cch];
__device__ __nv_bfloat16 g_Ylo[(size_t)Nn * HWX * Cch];
__device__ float g_cosM[(size_t)Nn * HWX * HWX];         // 512 MB cosine matrix
__device__ unsigned g_rmaxk[Nn * HWX];                   // row-max keys (fused epilogue)
__device__ float g_rA[Nn * HWX];
__device__ float g_rB[Nn * HWX];
__device__ unsigned g_cmax[Nn * HWX];

// ---------------- helpers ----------------
__device__ __forceinline__ float fexp2(float x) {
    x = fmaxf(x, -80.0f);
    float fx = x + 12582912.0f;
    float r  = x - (fx - 12582912.0f);
    int   n  = __float_as_int(fx) - 0x4B400000;
    float p  = 0.69314718056f + r * (0.2402265069f + r * (0.0555041087f +
               r * (0.00961812911f + r * (0.00133335581f + r * 0.000154035304f))));
    p = 1.0f + r * p;
    return __int_as_float(__float_as_int(p) + (n << 23));
}
__device__ __forceinline__ unsigned fkey(float f) {
    unsigned u = __float_as_uint(f);
    return (u & 0x80000000u) ? ~u : (u | 0x80000000u);
}
__device__ __forceinline__ float funkey(unsigned k) {
    return __uint_as_float((k & 0x80000000u) ? (k & 0x7fffffffu) : ~k);
}
__device__ __forceinline__ uint32_t smem_u32(const void* p) {
    uint32_t a;
    asm("{ .reg .u64 t; cvta.to.shared.u64 t, %1; cvt.u32.u64 %0, t; }" : "=r"(a) : "l"(p));
    return a;
}
__device__ __forceinline__ void cpa16(uint32_t s, const void* g) {
    asm volatile("cp.async.cg.shared.global [%0], [%1], 16;\n" :: "r"(s), "l"(g));
}
__device__ __forceinline__ void ldsm4(uint32_t* r, uint32_t a) {
    asm volatile("ldmatrix.sync.aligned.m8n8.x4.shared.b16 {%0,%1,%2,%3}, [%4];"
        : "=r"(r[0]), "=r"(r[1]), "=r"(r[2]), "=r"(r[3]) : "r"(a));
}
__device__ __forceinline__ void ldsm2(uint32_t* r, uint32_t a) {
    asm volatile("ldmatrix.sync.aligned.m8n8.x2.shared.b16 {%0,%1}, [%2];"
        : "=r"(r[0]), "=r"(r[1]) : "r"(a));
}
__device__ __forceinline__ void mma16816(float* d, const uint32_t* a, const uint32_t* b) {
    asm volatile("mma.sync.aligned.m16n8k16.row.col.f32.bf16.bf16.f32 "
        "{%0,%1,%2,%3}, {%4,%5,%6,%7}, {%8,%9}, {%0,%1,%2,%3};"
        : "+f"(d[0]), "+f"(d[1]), "+f"(d[2]), "+f"(d[3])
        : "r"(a[0]), "r"(a[1]), "r"(a[2]), "r"(a[3]), "r"(b[0]), "r"(b[1]));
}

// ---------------- kernels ----------------
__global__ void k_init() {
    int idx = blockIdx.x * 256 + threadIdx.x;
    if (idx < Nn * HWX) { g_cmax[idx] = 0u; g_rmaxk[idx] = 0u; }  // key-space -inf
}

__global__ void k_mu(const float* __restrict__ y) {
    int c = blockIdx.x, tid = threadIdx.x;
    float s = 0.f;
    for (int n = 0; n < Nn; n++) {
        const float* p = y + ((size_t)n * Cch + c) * HWX;
        for (int t = tid; t < HWX; t += 256) s += p[t];
    }
    __shared__ float red[256];
    red[tid] = s; __syncthreads();
    for (int o = 128; o > 0; o >>= 1) { if (tid < o) red[tid] += red[tid + o]; __syncthreads(); }
    if (tid == 0) g_mu[c] = red[0] * (1.0f / (Nn * HWX));
}

__global__ void k_norm(const float* __restrict__ x, const float* __restrict__ y) {
    int n = blockIdx.y;
    int i = blockIdx.x * 256 + threadIdx.x;
    __shared__ float smu[Cch];
    smu[threadIdx.x] = g_mu[threadIdx.x];
    __syncthreads();
    const float* xb = x + (size_t)n * Cch * HWX + i;
    const float* yb = y + (size_t)n * Cch * HWX + i;
    float sx = 0.f, sy = 0.f;
#pragma unroll 4
    for (int c = 0; c < Cch; c++) {
        float m  = smu[c];
        float xv = xb[(size_t)c * HWX] - m;
        float yv = yb[(size_t)c * HWX] - m;
        sx = fmaf(xv, xv, sx);
        sy = fmaf(yv, yv, sy);
    }
    g_invnx[n * HWX + i] = rsqrtf(sx);
    g_invny[n * HWX + i] = rsqrtf(sy);
}

// transpose (n,c,hw) -> (n,hw,c), normalize, split to bf16 hi+lo
__global__ void k_trans(const float* __restrict__ x, const float* __restrict__ y) {
    int n = blockIdx.z, c0 = blockIdx.y * 32, h0 = blockIdx.x * 32;
    __shared__ float tx[32][33], tyv[32][33];
    for (int r = threadIdx.y; r < 32; r += 8) {
        int c = c0 + r, h = h0 + threadIdx.x;
        float m = g_mu[c];
        size_t off = ((size_t)n * Cch + c) * HWX + h;
        tx[r][threadIdx.x]  = x[off] - m;
        tyv[r][threadIdx.x] = y[off] - m;
    }
    __syncthreads();
    for (int r = threadIdx.y; r < 32; r += 8) {
        int h = h0 + r, c = c0 + threadIdx.x;
        size_t off = ((size_t)n * HWX + h) * Cch + c;
        float vx = tx[threadIdx.x][r]  * g_invnx[n * HWX + h];
        float vy = tyv[threadIdx.x][r] * g_invny[n * HWX + h];
        __nv_bfloat16 xh = __float2bfloat16(vx);
        __nv_bfloat16 yh = __float2bfloat16(vy);
        g_Xhi[off] = xh; g_Xlo[off] = __float2bfloat16(vx - __bfloat162float(xh));
        g_Yhi[off] = yh; g_Ylo[off] = __float2bfloat16(vy - __bfloat162float(yh));
    }
}

// issue cp.async for one K-chunk (A hi/lo 128x32, B hi/lo 128x32)
__device__ __forceinline__ void load_chunk(uint32_t sbase,
        const __nv_bfloat16* Xhi, const __nv_bfloat16* Xlo,
        const __nv_bfloat16* Yhi, const __nv_bfloat16* Ylo,
        int i0, int j0, int k0, int tid) {
#pragma unroll
    for (int q = 0; q < 2; q++) {
        int u = tid + q * 256;        // 0..511
        int r = u >> 2, s = u & 3;    // row, 16B segment
        uint32_t d = (uint32_t)(r * ROWB + s * 16);
        size_t goA = (size_t)(i0 + r) * Cch + k0 + s * 8;
        size_t goB = (size_t)(j0 + r) * Cch + k0 + s * 8;
        cpa16(sbase + OFF_AHI + d, Xhi + goA);
        cpa16(sbase + OFF_ALO + d, Xlo + goA);
        cpa16(sbase + OFF_BHI + d, Yhi + goB);
        cpa16(sbase + OFF_BLO + d, Ylo + goB);
    }
    asm volatile("cp.async.commit_group;\n" ::: "memory");
}

// HMMA GEMM: cos[n] = Xn * Yn^T (split bf16 3-pass), fused row-max
__global__ void __launch_bounds__(256, 1) k_gemm() {
    extern __shared__ char smem[];
    __shared__ unsigned srm[BM];
    uint32_t sb = smem_u32(smem);
    int tid = threadIdx.x;
    int n = blockIdx.z;
    int i0 = blockIdx.y * BM, j0 = blockIdx.x * BN;

    const __nv_bfloat16* Xhi = g_Xhi + (size_t)n * HWX * Cch;
    const __nv_bfloat16* Xlo = g_Xlo + (size_t)n * HWX * Cch;
    const __nv_bfloat16* Yhi = g_Yhi + (size_t)n * HWX * Cch;
    const __nv_bfloat16* Ylo = g_Ylo + (size_t)n * HWX * Cch;

    if (tid < BM) srm[tid] = 0u;

    int w = tid >> 5, lane = tid & 31;
    int wm = w & 1, wn = w >> 1;            // warp tile 64x32 at (wm*64, wn*32)

    // per-lane ldmatrix base offsets (bytes, within a stage)
    uint32_t aoff = (uint32_t)((wm * 64 + (lane & 15)) * ROWB + (lane >> 4) * 16);
    uint32_t boff = (uint32_t)((wn * 32 + (lane & 7)) * ROWB + ((lane >> 3) & 1) * 16);

    float acc[4][4][4];
#pragma unroll
    for (int a = 0; a < 4; a++)
#pragma unroll
        for (int b = 0; b < 4; b++)
#pragma unroll
            for (int c = 0; c < 4; c++) acc[a][b][c] = 0.f;

    load_chunk(sb, Xhi, Xlo, Yhi, Ylo, i0, j0, 0, tid);

    for (int c = 0; c < NCHUNK; c++) {
        uint32_t scur = sb + (uint32_t)(c & 1) * STAGE;
        if (c + 1 < NCHUNK) {
            load_chunk(sb + (uint32_t)((c + 1) & 1) * STAGE,
                       Xhi, Xlo, Yhi, Ylo, i0, j0, (c + 1) * BK, tid);
            asm volatile("cp.async.wait_group 1;\n" ::: "memory");
        } else {
            asm volatile("cp.async.wait_group 0;\n" ::: "memory");
        }
        __syncthreads();

#pragma unroll
        for (int k16 = 0; k16 < 2; k16++) {
            uint32_t ka = scur + aoff + k16 * 32;
            uint32_t kb = scur + boff + k16 * 32;
            uint32_t ahi[4][4], alo[4][4], bhi[4][2], blo[4][2];
#pragma unroll
            for (int mi = 0; mi < 4; mi++) {
                ldsm4(ahi[mi], ka + OFF_AHI + mi * 16 * ROWB);
                ldsm4(alo[mi], ka + OFF_ALO + mi * 16 * ROWB);
            }
#pragma unroll
            for (int ni = 0; ni < 4; ni++) {
                ldsm2(bhi[ni], kb + OFF_BHI + ni * 8 * ROWB);
                ldsm2(blo[ni], kb + OFF_BLO + ni * 8 * ROWB);
            }
#pragma unroll
            for (int mi = 0; mi < 4; mi++)
#pragma unroll
                for (int ni = 0; ni < 4; ni++) {
                    mma16816(acc[mi][ni], ahi[mi], bhi[ni]);
                    mma16816(acc[mi][ni], ahi[mi], blo[ni]);
                    mma16816(acc[mi][ni], alo[mi], bhi[ni]);
                }
        }
        __syncthreads();   // stage will be overwritten next iteration
    }

    // epilogue: store C + fused row-max (smem-staged)
    int rl0 = wm * 64 + (lane >> 2);           // local row (first half of tile)
    int cb  = j0 + wn * 32 + 2 * (lane & 3);   // column base
#pragma unroll
    for (int mi = 0; mi < 4; mi++) {
        int r1 = rl0 + mi * 16, r2 = r1 + 8;
        float m1 = -1e30f, m2 = -1e30f;
        float* p1 = g_cosM + ((size_t)n * HWX + i0 + r1) * HWX + cb;
        float* p2 = g_cosM + ((size_t)n * HWX + i0 + r2) * HWX + cb;
#pragma unroll
        for (int ni = 0; ni < 4; ni++) {
            float c0 = acc[mi][ni][0], c1 = acc[mi][ni][1];
            float c2 = acc[mi][ni][2], c3 = acc[mi][ni][3];
            m1 = fmaxf(m1, fmaxf(c0, c1));
            m2 = fmaxf(m2, fmaxf(c2, c3));
            *(float2*)(p1 + ni * 8) = make_float2(c0, c1);
            *(float2*)(p2 + ni * 8) = make_float2(c2, c3);
        }
        atomicMax(&srm[r1], fkey(m1));
        atomicMax(&srm[r2], fkey(m2));
    }
    __syncthreads();
    if (tid < BM) atomicMax(&g_rmaxk[n * HWX + i0 + tid], srm[tid]);
}

// per-row sums (rowmax already computed in GEMM epilogue)
__global__ void k_row() {
    int n = blockIdx.y, i = blockIdx.x, tid = threadIdx.x;
    const float4* row = (const float4*)(g_cosM + ((size_t)n * HWX + i) * HWX);
    float dmp = 1.0f - funkey(g_rmaxk[n * HWX + i]) + EPSF;
    float inv = 2.0f / dmp;
    float a2  = inv * LOG2E;
    float b2  = (2.0f - inv) * LOG2E;
    float s = 0.f;
    for (int j = tid; j < HWX / 4; j += 256) {
        float4 v = row[j];
        s += fexp2(fmaf(a2, v.x, b2)) + fexp2(fmaf(a2, v.y, b2))
           + fexp2(fmaf(a2, v.z, b2)) + fexp2(fmaf(a2, v.w, b2));
    }
    __shared__ float red[256];
    red[tid] = s; __syncthreads();
    for (int o = 128; o > 0; o >>= 1) { if (tid < o) red[tid] += red[tid + o]; __syncthreads(); }
    if (tid == 0) {
        g_rA[n * HWX + i] = inv;
        g_rB[n * HWX + i] = (2.0f - inv) - logf(red[0]);
    }
}

__global__ void __launch_bounds__(128) k_colmax() {
    int n = blockIdx.z;
    int j = blockIdx.x * 128 + threadIdx.x;
    int i0 = blockIdx.y * 128;
    __shared__ float sA[128], sB[128];
    sA[threadIdx.x] = g_rA[n * HWX + i0 + threadIdx.x];
    sB[threadIdx.x] = g_rB[n * HWX + i0 + threadIdx.x];
    __syncthreads();
    const float* base = g_cosM + ((size_t)n * HWX + i0) * HWX + j;
    float best = -1e30f;
#pragma unroll 4
    for (int ii = 0; ii < 128; ii++) {
        float cv = base[(size_t)ii * HWX];
        best = fmaxf(best, fmaf(sA[ii], cv, sB[ii]));
    }
    atomicMax(&g_cmax[n * HWX + j], fkey(best));
}

__global__ void k_final(float* __restrict__ out) {
    int tid = threadIdx.x;
    __shared__ float red[256];
    float acc = 0.f;
    for (int n = 0; n < Nn; n++) {
        float s = 0.f;
        for (int j = tid; j < HWX; j += 256) s += expf(funkey(g_cmax[n * HWX + j]));
        red[tid] = s; __syncthreads();
        for (int o = 128; o > 0; o >>= 1) { if (tid < o) red[tid] += red[tid + o]; __syncthreads(); }
        if (tid == 0) {
            float ccx = red[0] * (1.0f / HWX);
            acc += -logf(ccx + EPSF);
        }
        __syncthreads();
    }
    if (tid == 0) out[0] = acc * (1.0f / Nn);
}

// ---------------- launcher ----------------
extern "C" void kernel_launch(void* const* d_in, const int* in_sizes, int n_in,
                              void* d_out, int out_size) {
    const float* x = (const float*)d_in[0];
    const float* y = (const float*)d_in[1];
    float* out = (float*)d_out;

    cudaFuncSetAttribute(k_gemm, cudaFuncAttributeMaxDynamicSharedMemorySize, SMEM_DYN);

    k_init<<<(Nn * HWX + 255) / 256, 256>>>();
    k_mu<<<Cch, 256>>>(y);
    k_norm<<<dim3(HWX / 256, Nn), 256>>>(x, y);
    k_trans<<<dim3(HWX / 32, Cch / 32, Nn), dim3(32, 8)>>>(x, y);
    k_gemm<<<dim3(HWX / BN, HWX / BM, Nn), 256, SMEM_DYN>>>();
    k_row<<<dim3(HWX, Nn), 256>>>();
    k_colmax<<<dim3(HWX / 128, HWX / 128, Nn), 128>>>();
    k_final<<<1, 256>>>(out);
}

// round 11
// speedup vs baseline: 2.8461x; 1.9055x over previous
#include <cuda_runtime.h>
#include <cuda_bf16.h>
#include <cstdint>

#define Nn   8
#define Cch  256
#define HWX  4096
#define EPSF 1e-6f
#define LOG2E 1.44269504088896340736f

// GEMM tiling
#define BM 128
#define BN 128
#define BK 32
#define NCHUNK (Cch / BK)   // 8

// smem: row stride 80B (64B data + 16B pad) -> conflict-free ldmatrix
#define ROWB   80
#define OFF_AHI 0
#define OFF_BHI (128 * ROWB)
#define OFF_BLO (2 * 128 * ROWB)
#define STAGE   (3 * 128 * ROWB)       // 30720
#define NSTAGE  3
#define SMEM_DYN (NSTAGE * STAGE)      // 92160

// ---------------- device scratch ----------------
__device__ float g_mu[Cch];
__device__ float g_invnx[Nn * HWX];
__device__ float g_invny[Nn * HWX];
__device__ __nv_bfloat16 g_Xhi[(size_t)Nn * HWX * Cch];  // [n][hw][c] K-major
__device__ __nv_bfloat16 g_Yhi[(size_t)Nn * HWX * Cch];
__device__ __nv_bfloat16 g_Ylo[(size_t)Nn * HWX * Cch];
__device__ float g_cosM[(size_t)Nn * HWX * HWX];         // 512 MB cosine matrix
__device__ unsigned g_rmaxk[Nn * HWX];                   // row-max keys (fused epilogue)
__device__ float g_rA[Nn * HWX];
__device__ float g_rB[Nn * HWX];
__device__ unsigned g_cmax[Nn * HWX];

// ---------------- helpers ----------------
__device__ __forceinline__ float fexp2(float x) {
    x = fmaxf(x, -80.0f);
    float fx = x + 12582912.0f;
    float r  = x - (fx - 12582912.0f);
    int   n  = __float_as_int(fx) - 0x4B400000;
    float p  = 0.69314718056f + r * (0.2402265069f + r * (0.0555041087f +
               r * (0.00961812911f + r * (0.00133335581f + r * 0.000154035304f))));
    p = 1.0f + r * p;
    return __int_as_float(__float_as_int(p) + (n << 23));
}
__device__ __forceinline__ unsigned fkey(float f) {
    unsigned u = __float_as_uint(f);
    return (u & 0x80000000u) ? ~u : (u | 0x80000000u);
}
__device__ __forceinline__ float funkey(unsigned k) {
    return __uint_as_float((k & 0x80000000u) ? (k & 0x7fffffffu) : ~k);
}
__device__ __forceinline__ uint32_t smem_u32(const void* p) {
    uint32_t a;
    asm("{ .reg .u64 t; cvta.to.shared.u64 t, %1; cvt.u32.u64 %0, t; }" : "=r"(a) : "l"(p));
    return a;
}
__device__ __forceinline__ void cpa16(uint32_t s, const void* g) {
    asm volatile("cp.async.cg.shared.global [%0], [%1], 16;\n" :: "r"(s), "l"(g));
}
__device__ __forceinline__ void ldsm4(uint32_t* r, uint32_t a) {
    asm volatile("ldmatrix.sync.aligned.m8n8.x4.shared.b16 {%0,%1,%2,%3}, [%4];"
        : "=r"(r[0]), "=r"(r[1]), "=r"(r[2]), "=r"(r[3]) : "r"(a));
}
__device__ __forceinline__ void ldsm2(uint32_t* r, uint32_t a) {
    asm volatile("ldmatrix.sync.aligned.m8n8.x2.shared.b16 {%0,%1}, [%2];"
        : "=r"(r[0]), "=r"(r[1]) : "r"(a));
}
__device__ __forceinline__ void mma16816(float* d, const uint32_t* a, const uint32_t* b) {
    asm volatile("mma.sync.aligned.m16n8k16.row.col.f32.bf16.bf16.f32 "
        "{%0,%1,%2,%3}, {%4,%5,%6,%7}, {%8,%9}, {%0,%1,%2,%3};"
        : "+f"(d[0]), "+f"(d[1]), "+f"(d[2]), "+f"(d[3])
        : "r"(a[0]), "r"(a[1]), "r"(a[2]), "r"(a[3]), "r"(b[0]), "r"(b[1]));
}

// ---------------- kernels ----------------
__global__ void k_init() {
    int idx = blockIdx.x * 256 + threadIdx.x;
    if (idx < Nn * HWX) { g_cmax[idx] = 0u; g_rmaxk[idx] = 0u; }
}

__global__ void k_mu(const float* __restrict__ y) {
    int c = blockIdx.x, tid = threadIdx.x;
    float s = 0.f;
    for (int n = 0; n < Nn; n++) {
        const float* p = y + ((size_t)n * Cch + c) * HWX;
        for (int t = tid; t < HWX; t += 256) s += p[t];
    }
    __shared__ float red[256];
    red[tid] = s; __syncthreads();
    for (int o = 128; o > 0; o >>= 1) { if (tid < o) red[tid] += red[tid + o]; __syncthreads(); }
    if (tid == 0) g_mu[c] = red[0] * (1.0f / (Nn * HWX));
}

__global__ void k_norm(const float* __restrict__ x, const float* __restrict__ y) {
    int n = blockIdx.y;
    int i = blockIdx.x * 256 + threadIdx.x;
    __shared__ float smu[Cch];
    smu[threadIdx.x] = g_mu[threadIdx.x];
    __syncthreads();
    const float* xb = x + (size_t)n * Cch * HWX + i;
    const float* yb = y + (size_t)n * Cch * HWX + i;
    float sx = 0.f, sy = 0.f;
#pragma unroll 4
    for (int c = 0; c < Cch; c++) {
        float m  = smu[c];
        float xv = xb[(size_t)c * HWX] - m;
        float yv = yb[(size_t)c * HWX] - m;
        sx = fmaf(xv, xv, sx);
        sy = fmaf(yv, yv, sy);
    }
    g_invnx[n * HWX + i] = rsqrtf(sx);
    g_invny[n * HWX + i] = rsqrtf(sy);
}

// transpose (n,c,hw) -> (n,hw,c), normalize; X -> bf16 hi, Y -> bf16 hi+lo
__global__ void k_trans(const float* __restrict__ x, const float* __restrict__ y) {
    int n = blockIdx.z, c0 = blockIdx.y * 32, h0 = blockIdx.x * 32;
    __shared__ float tx[32][33], tyv[32][33];
    for (int r = threadIdx.y; r < 32; r += 8) {
        int c = c0 + r, h = h0 + threadIdx.x;
        float m = g_mu[c];
        size_t off = ((size_t)n * Cch + c) * HWX + h;
        tx[r][threadIdx.x]  = x[off] - m;
        tyv[r][threadIdx.x] = y[off] - m;
    }
    __syncthreads();
    for (int r = threadIdx.y; r < 32; r += 8) {
        int h = h0 + r, c = c0 + threadIdx.x;
        size_t off = ((size_t)n * HWX + h) * Cch + c;
        float vx = tx[threadIdx.x][r]  * g_invnx[n * HWX + h];
        float vy = tyv[threadIdx.x][r] * g_invny[n * HWX + h];
        __nv_bfloat16 yh = __float2bfloat16(vy);
        g_Xhi[off] = __float2bfloat16(vx);
        g_Yhi[off] = yh;
        g_Ylo[off] = __float2bfloat16(vy - __bfloat162float(yh));
    }
}

// cp.async one K-chunk: A hi (128x32), B hi/lo (128x32 each)
__device__ __forceinline__ void load_chunk(uint32_t sbase,
        const __nv_bfloat16* Xhi, const __nv_bfloat16* Yhi, const __nv_bfloat16* Ylo,
        int i0, int j0, int k0, int tid) {
#pragma unroll
    for (int q = 0; q < 2; q++) {
        int u = tid + q * 256;        // 0..511
        int r = u >> 2, s = u & 3;    // row, 16B segment
        uint32_t d = (uint32_t)(r * ROWB + s * 16);
        size_t goA = (size_t)(i0 + r) * Cch + k0 + s * 8;
        size_t goB = (size_t)(j0 + r) * Cch + k0 + s * 8;
        cpa16(sbase + OFF_AHI + d, Xhi + goA);
        cpa16(sbase + OFF_BHI + d, Yhi + goB);
        cpa16(sbase + OFF_BLO + d, Ylo + goB);
    }
    asm volatile("cp.async.commit_group;\n" ::: "memory");
}

// HMMA GEMM: cos[n] = Xh * (Yh + Yl)^T (2-pass), fused row-max, 3-stage pipeline
__global__ void __launch_bounds__(256, 1) k_gemm() {
    extern __shared__ char smem[];
    __shared__ unsigned srm[BM];
    uint32_t sb = smem_u32(smem);
    int tid = threadIdx.x;
    int n = blockIdx.z;
    int i0 = blockIdx.y * BM, j0 = blockIdx.x * BN;

    const __nv_bfloat16* Xhi = g_Xhi + (size_t)n * HWX * Cch;
    const __nv_bfloat16* Yhi = g_Yhi + (size_t)n * HWX * Cch;
    const __nv_bfloat16* Ylo = g_Ylo + (size_t)n * HWX * Cch;

    if (tid < BM) srm[tid] = 0u;

    int w = tid >> 5, lane = tid & 31;
    int wm = w & 1, wn = w >> 1;            // warp tile 64x32 at (wm*64, wn*32)

    uint32_t aoff = (uint32_t)((wm * 64 + (lane & 15)) * ROWB + (lane >> 4) * 16);
    uint32_t boff = (uint32_t)((wn * 32 + (lane & 7)) * ROWB + ((lane >> 3) & 1) * 16);

    float acc[4][4][4];
#pragma unroll
    for (int a = 0; a < 4; a++)
#pragma unroll
        for (int b = 0; b < 4; b++)
#pragma unroll
            for (int c = 0; c < 4; c++) acc[a][b][c] = 0.f;

    load_chunk(sb,         Xhi, Yhi, Ylo, i0, j0, 0,  tid);
    load_chunk(sb + STAGE, Xhi, Yhi, Ylo, i0, j0, BK, tid);

    for (int c = 0; c < NCHUNK; c++) {
        uint32_t scur = sb + (uint32_t)(c % NSTAGE) * STAGE;
        if (c + 2 < NCHUNK) {
            load_chunk(sb + (uint32_t)((c + 2) % NSTAGE) * STAGE,
                       Xhi, Yhi, Ylo, i0, j0, (c + 2) * BK, tid);
            asm volatile("cp.async.wait_group 2;\n" ::: "memory");
        } else if (c + 1 < NCHUNK) {
            asm volatile("cp.async.wait_group 1;\n" ::: "memory");
        } else {
            asm volatile("cp.async.wait_group 0;\n" ::: "memory");
        }
        __syncthreads();

#pragma unroll
        for (int k16 = 0; k16 < 2; k16++) {
            uint32_t ka = scur + aoff + k16 * 32;
            uint32_t kb = scur + boff + k16 * 32;
            uint32_t ahi[4][4], bhi[4][2], blo[4][2];
#pragma unroll
            for (int mi = 0; mi < 4; mi++)
                ldsm4(ahi[mi], ka + OFF_AHI + mi * 16 * ROWB);
#pragma unroll
            for (int ni = 0; ni < 4; ni++) {
                ldsm2(bhi[ni], kb + OFF_BHI + ni * 8 * ROWB);
                ldsm2(blo[ni], kb + OFF_BLO + ni * 8 * ROWB);
            }
#pragma unroll
            for (int mi = 0; mi < 4; mi++)
#pragma unroll
                for (int ni = 0; ni < 4; ni++) {
                    mma16816(acc[mi][ni], ahi[mi], bhi[ni]);
                    mma16816(acc[mi][ni], ahi[mi], blo[ni]);
                }
        }
        __syncthreads();   // protect stage before its reuse by a later load
    }

    // epilogue: store C + fused row-max (smem-staged)
    int rl0 = wm * 64 + (lane >> 2);
    int cb  = j0 + wn * 32 + 2 * (lane & 3);
#pragma unroll
    for (int mi = 0; mi < 4; mi++) {
        int r1 = rl0 + mi * 16, r2 = r1 + 8;
        float m1 = -1e30f, m2 = -1e30f;
        float* p1 = g_cosM + ((size_t)n * HWX + i0 + r1) * HWX + cb;
        float* p2 = g_cosM + ((size_t)n * HWX + i0 + r2) * HWX + cb;
#pragma unroll
        for (int ni = 0; ni < 4; ni++) {
            float c0 = acc[mi][ni][0], c1 = acc[mi][ni][1];
            float c2 = acc[mi][ni][2], c3 = acc[mi][ni][3];
            m1 = fmaxf(m1, fmaxf(c0, c1));
            m2 = fmaxf(m2, fmaxf(c2, c3));
            *(float2*)(p1 + ni * 8) = make_float2(c0, c1);
            *(float2*)(p2 + ni * 8) = make_float2(c2, c3);
        }
        atomicMax(&srm[r1], fkey(m1));
        atomicMax(&srm[r2], fkey(m2));
    }
    __syncthreads();
    if (tid < BM) atomicMax(&g_rmaxk[n * HWX + i0 + tid], srm[tid]);
}

// per-row sums (rowmax already computed in GEMM epilogue)
__global__ void k_row() {
    int n = blockIdx.y, i = blockIdx.x, tid = threadIdx.x;
    const float4* row = (const float4*)(g_cosM + ((size_t)n * HWX + i) * HWX);
    float dmp = 1.0f - funkey(g_rmaxk[n * HWX + i]) + EPSF;
    float inv = 2.0f / dmp;
    float a2  = inv * LOG2E;
    float b2  = (2.0f - inv) * LOG2E;
    float s = 0.f;
    for (int j = tid; j < HWX / 4; j += 256) {
        float4 v = row[j];
        s += fexp2(fmaf(a2, v.x, b2)) + fexp2(fmaf(a2, v.y, b2))
           + fexp2(fmaf(a2, v.z, b2)) + fexp2(fmaf(a2, v.w, b2));
    }
    __shared__ float red[256];
    red[tid] = s; __syncthreads();
    for (int o = 128; o > 0; o >>= 1) { if (tid < o) red[tid] += red[tid + o]; __syncthreads(); }
    if (tid == 0) {
        g_rA[n * HWX + i] = inv;
        g_rB[n * HWX + i] = (2.0f - inv) - logf(red[0]);
    }
}

__global__ void __launch_bounds__(128) k_colmax() {
    int n = blockIdx.z;
    int j = blockIdx.x * 128 + threadIdx.x;
    int i0 = blockIdx.y * 128;
    __shared__ float sA[128], sB[128];
    sA[threadIdx.x] = g_rA[n * HWX + i0 + threadIdx.x];
    sB[threadIdx.x] = g_rB[n * HWX + i0 + threadIdx.x];
    __syncthreads();
    const float* base = g_cosM + ((size_t)n * HWX + i0) * HWX + j;
    float best = -1e30f;
#pragma unroll 4
    for (int ii = 0; ii < 128; ii++) {
        float cv = base[(size_t)ii * HWX];
        best = fmaxf(best, fmaf(sA[ii], cv, sB[ii]));
    }
    atomicMax(&g_cmax[n * HWX + j], fkey(best));
}

__global__ void k_final(float* __restrict__ out) {
    int tid = threadIdx.x;
    __shared__ float red[256];
    float acc = 0.f;
    for (int n = 0; n < Nn; n++) {
        float s = 0.f;
        for (int j = tid; j < HWX; j += 256) s += expf(funkey(g_cmax[n * HWX + j]));
        red[tid] = s; __syncthreads();
        for (int o = 128; o > 0; o >>= 1) { if (tid < o) red[tid] += red[tid + o]; __syncthreads(); }
        if (tid == 0) {
            float ccx = red[0] * (1.0f / HWX);
            acc += -logf(ccx + EPSF);
        }
        __syncthreads();
    }
    if (tid == 0) out[0] = acc * (1.0f / Nn);
}

// ---------------- launcher ----------------
extern "C" void kernel_launch(void* const* d_in, const int* in_sizes, int n_in,
                              void* d_out, int out_size) {
    const float* x = (const float*)d_in[0];
    const float* y = (const float*)d_in[1];
    float* out = (float*)d_out;

    cudaFuncSetAttribute(k_gemm, cudaFuncAttributeMaxDynamicSharedMemorySize, SMEM_DYN);

    k_init<<<(Nn * HWX + 255) / 256, 256>>>();
    k_mu<<<Cch, 256>>>(y);
    k_norm<<<dim3(HWX / 256, Nn), 256>>>(x, y);
    k_trans<<<dim3(HWX / 32, Cch / 32, Nn), dim3(32, 8)>>>(x, y);
    k_gemm<<<dim3(HWX / BN, HWX / BM, Nn), 256, SMEM_DYN>>>();
    k_row<<<dim3(HWX, Nn), 256>>>();
    k_colmax<<<dim3(HWX / 128, HWX / 128, Nn), 128>>>();
    k_final<<<1, 256>>>(out);
}

// round 12
// speedup vs baseline: 4.3044x; 1.5124x over previous
#include <cuda_runtime.h>
#include <cuda_bf16.h>
#include <cuda_fp16.h>
#include <cstdint>

#define Nn   8
#define Cch  256
#define HWX  4096
#define EPSF 1e-6f
#define LOG2E 1.44269504088896340736f

// GEMM tiling
#define BM 128
#define BN 128
#define BK 32
#define NCHUNK (Cch / BK)   // 8

// smem: row stride 80B (64B data + 16B pad) -> conflict-free ldmatrix
#define ROWB   80
#define OFF_AHI 0
#define OFF_BHI (128 * ROWB)
#define STAGE   (2 * 128 * ROWB)       // 20480
#define NSTAGE  3
#define SMEM_DYN (NSTAGE * STAGE)      // 61440

// ---------------- device scratch ----------------
__device__ float g_mu[Cch];
__device__ float g_invnx[Nn * HWX];
__device__ float g_invny[Nn * HWX];
__device__ __nv_bfloat16 g_Xhi[(size_t)Nn * HWX * Cch];  // [n][hw][c] K-major
__device__ __nv_bfloat16 g_Yhi[(size_t)Nn * HWX * Cch];
__device__ __half g_cosM[(size_t)Nn * HWX * HWX];        // 256 MB cosine matrix (fp16)
__device__ unsigned g_rmaxk[Nn * HWX];                   // row-max keys (fused epilogue)
__device__ float g_rA[Nn * HWX];
__device__ float g_rB[Nn * HWX];
__device__ unsigned g_cmax[Nn * HWX];

// ---------------- helpers ----------------
__device__ __forceinline__ float fexp2(float x) {
    x = fmaxf(x, -80.0f);
    float fx = x + 12582912.0f;
    float r  = x - (fx - 12582912.0f);
    int   n  = __float_as_int(fx) - 0x4B400000;
    float p  = 0.69314718056f + r * (0.2402265069f + r * (0.0555041087f +
               r * (0.00961812911f + r * (0.00133335581f + r * 0.000154035304f))));
    p = 1.0f + r * p;
    return __int_as_float(__float_as_int(p) + (n << 23));
}
__device__ __forceinline__ unsigned fkey(float f) {
    unsigned u = __float_as_uint(f);
    return (u & 0x80000000u) ? ~u : (u | 0x80000000u);
}
__device__ __forceinline__ float funkey(unsigned k) {
    return __uint_as_float((k & 0x80000000u) ? (k & 0x7fffffffu) : ~k);
}
__device__ __forceinline__ uint32_t smem_u32(const void* p) {
    uint32_t a;
    asm("{ .reg .u64 t; cvta.to.shared.u64 t, %1; cvt.u32.u64 %0, t; }" : "=r"(a) : "l"(p));
    return a;
}
__device__ __forceinline__ void cpa16(uint32_t s, const void* g) {
    asm volatile("cp.async.cg.shared.global [%0], [%1], 16;\n" :: "r"(s), "l"(g));
}
__device__ __forceinline__ void ldsm4(uint32_t* r, uint32_t a) {
    asm volatile("ldmatrix.sync.aligned.m8n8.x4.shared.b16 {%0,%1,%2,%3}, [%4];"
        : "=r"(r[0]), "=r"(r[1]), "=r"(r[2]), "=r"(r[3]) : "r"(a));
}
__device__ __forceinline__ void ldsm2(uint32_t* r, uint32_t a) {
    asm volatile("ldmatrix.sync.aligned.m8n8.x2.shared.b16 {%0,%1}, [%2];"
        : "=r"(r[0]), "=r"(r[1]) : "r"(a));
}
__device__ __forceinline__ void mma16816(float* d, const uint32_t* a, const uint32_t* b) {
    asm volatile("mma.sync.aligned.m16n8k16.row.col.f32.bf16.bf16.f32 "
        "{%0,%1,%2,%3}, {%4,%5,%6,%7}, {%8,%9}, {%0,%1,%2,%3};"
        : "+f"(d[0]), "+f"(d[1]), "+f"(d[2]), "+f"(d[3])
        : "r"(a[0]), "r"(a[1]), "r"(a[2]), "r"(a[3]), "r"(b[0]), "r"(b[1]));
}

// ---------------- kernels ----------------
__global__ void k_init() {
    int idx = blockIdx.x * 256 + threadIdx.x;
    if (idx < Nn * HWX) { g_cmax[idx] = 0u; g_rmaxk[idx] = 0u; }
}

__global__ void k_mu(const float* __restrict__ y) {
    int c = blockIdx.x, tid = threadIdx.x;
    float s = 0.f;
    for (int n = 0; n < Nn; n++) {
        const float* p = y + ((size_t)n * Cch + c) * HWX;
        for (int t = tid; t < HWX; t += 256) s += p[t];
    }
    __shared__ float red[256];
    red[tid] = s; __syncthreads();
    for (int o = 128; o > 0; o >>= 1) { if (tid < o) red[tid] += red[tid + o]; __syncthreads(); }
    if (tid == 0) g_mu[c] = red[0] * (1.0f / (Nn * HWX));
}

__global__ void k_norm(const float* __restrict__ x, const float* __restrict__ y) {
    int n = blockIdx.y;
    int i = blockIdx.x * 256 + threadIdx.x;
    __shared__ float smu[Cch];
    smu[threadIdx.x] = g_mu[threadIdx.x];
    __syncthreads();
    const float* xb = x + (size_t)n * Cch * HWX + i;
    const float* yb = y + (size_t)n * Cch * HWX + i;
    float sx = 0.f, sy = 0.f;
#pragma unroll 4
    for (int c = 0; c < Cch; c++) {
        float m  = smu[c];
        float xv = xb[(size_t)c * HWX] - m;
        float yv = yb[(size_t)c * HWX] - m;
        sx = fmaf(xv, xv, sx);
        sy = fmaf(yv, yv, sy);
    }
    g_invnx[n * HWX + i] = rsqrtf(sx);
    g_invny[n * HWX + i] = rsqrtf(sy);
}

// transpose (n,c,hw) -> (n,hw,c), normalize; X,Y -> bf16
__global__ void k_trans(const float* __restrict__ x, const float* __restrict__ y) {
    int n = blockIdx.z, c0 = blockIdx.y * 32, h0 = blockIdx.x * 32;
    __shared__ float tx[32][33], tyv[32][33];
    for (int r = threadIdx.y; r < 32; r += 8) {
        int c = c0 + r, h = h0 + threadIdx.x;
        float m = g_mu[c];
        size_t off = ((size_t)n * Cch + c) * HWX + h;
        tx[r][threadIdx.x]  = x[off] - m;
        tyv[r][threadIdx.x] = y[off] - m;
    }
    __syncthreads();
    for (int r = threadIdx.y; r < 32; r += 8) {
        int h = h0 + r, c = c0 + threadIdx.x;
        size_t off = ((size_t)n * HWX + h) * Cch + c;
        g_Xhi[off] = __float2bfloat16(tx[threadIdx.x][r]  * g_invnx[n * HWX + h]);
        g_Yhi[off] = __float2bfloat16(tyv[threadIdx.x][r] * g_invny[n * HWX + h]);
    }
}

// cp.async one K-chunk: A (128x32), B (128x32) bf16
__device__ __forceinline__ void load_chunk(uint32_t sbase,
        const __nv_bfloat16* Xhi, const __nv_bfloat16* Yhi,
        int i0, int j0, int k0, int tid) {
#pragma unroll
    for (int q = 0; q < 2; q++) {
        int u = tid + q * 256;        // 0..511
        int r = u >> 2, s = u & 3;    // row, 16B segment
        uint32_t d = (uint32_t)(r * ROWB + s * 16);
        size_t goA = (size_t)(i0 + r) * Cch + k0 + s * 8;
        size_t goB = (size_t)(j0 + r) * Cch + k0 + s * 8;
        cpa16(sbase + OFF_AHI + d, Xhi + goA);
        cpa16(sbase + OFF_BHI + d, Yhi + goB);
    }
    asm volatile("cp.async.commit_group;\n" ::: "memory");
}

// HMMA GEMM: cos[n] = X * Y^T (bf16), fp16 output, fused row-max, 3-stage pipeline
__global__ void __launch_bounds__(256, 2) k_gemm() {
    extern __shared__ char smem[];
    __shared__ unsigned srm[BM];
    uint32_t sb = smem_u32(smem);
    int tid = threadIdx.x;
    int n = blockIdx.z;
    int i0 = blockIdx.y * BM, j0 = blockIdx.x * BN;

    const __nv_bfloat16* Xhi = g_Xhi + (size_t)n * HWX * Cch;
    const __nv_bfloat16* Yhi = g_Yhi + (size_t)n * HWX * Cch;

    if (tid < BM) srm[tid] = 0u;

    int w = tid >> 5, lane = tid & 31;
    int wm = w & 1, wn = w >> 1;            // warp tile 64x32 at (wm*64, wn*32)

    uint32_t aoff = (uint32_t)((wm * 64 + (lane & 15)) * ROWB + (lane >> 4) * 16);
    uint32_t boff = (uint32_t)((wn * 32 + (lane & 7)) * ROWB + ((lane >> 3) & 1) * 16);

    float acc[4][4][4];
#pragma unroll
    for (int a = 0; a < 4; a++)
#pragma unroll
        for (int b = 0; b < 4; b++)
#pragma unroll
            for (int c = 0; c < 4; c++) acc[a][b][c] = 0.f;

    load_chunk(sb,         Xhi, Yhi, i0, j0, 0,  tid);
    load_chunk(sb + STAGE, Xhi, Yhi, i0, j0, BK, tid);

    for (int c = 0; c < NCHUNK; c++) {
        uint32_t scur = sb + (uint32_t)(c % NSTAGE) * STAGE;
        if (c + 2 < NCHUNK) {
            load_chunk(sb + (uint32_t)((c + 2) % NSTAGE) * STAGE,
                       Xhi, Yhi, i0, j0, (c + 2) * BK, tid);
            asm volatile("cp.async.wait_group 2;\n" ::: "memory");
        } else if (c + 1 < NCHUNK) {
            asm volatile("cp.async.wait_group 1;\n" ::: "memory");
        } else {
            asm volatile("cp.async.wait_group 0;\n" ::: "memory");
        }
        __syncthreads();

#pragma unroll
        for (int k16 = 0; k16 < 2; k16++) {
            uint32_t ka = scur + aoff + k16 * 32;
            uint32_t kb = scur + boff + k16 * 32;
            uint32_t ahi[4][4], bhi[4][2];
#pragma unroll
            for (int mi = 0; mi < 4; mi++)
                ldsm4(ahi[mi], ka + OFF_AHI + mi * 16 * ROWB);
#pragma unroll
            for (int ni = 0; ni < 4; ni++)
                ldsm2(bhi[ni], kb + OFF_BHI + ni * 8 * ROWB);
#pragma unroll
            for (int mi = 0; mi < 4; mi++)
#pragma unroll
                for (int ni = 0; ni < 4; ni++)
                    mma16816(acc[mi][ni], ahi[mi], bhi[ni]);
        }
        __syncthreads();
    }

    // epilogue: fp16 store + fused row-max over the ROUNDED values
    int rl0 = wm * 64 + (lane >> 2);
    int cb  = j0 + wn * 32 + 2 * (lane & 3);
#pragma unroll
    for (int mi = 0; mi < 4; mi++) {
        int r1 = rl0 + mi * 16, r2 = r1 + 8;
        float m1 = -1e30f, m2 = -1e30f;
        __half* p1 = g_cosM + ((size_t)n * HWX + i0 + r1) * HWX + cb;
        __half* p2 = g_cosM + ((size_t)n * HWX + i0 + r2) * HWX + cb;
#pragma unroll
        for (int ni = 0; ni < 4; ni++) {
            __half2 h1 = __floats2half2_rn(acc[mi][ni][0], acc[mi][ni][1]);
            __half2 h2 = __floats2half2_rn(acc[mi][ni][2], acc[mi][ni][3]);
            float2 f1 = __half22float2(h1);
            float2 f2 = __half22float2(h2);
            m1 = fmaxf(m1, fmaxf(f1.x, f1.y));
            m2 = fmaxf(m2, fmaxf(f2.x, f2.y));
            *(__half2*)(p1 + ni * 8) = h1;
            *(__half2*)(p2 + ni * 8) = h2;
        }
        atomicMax(&srm[r1], fkey(m1));
        atomicMax(&srm[r2], fkey(m2));
    }
    __syncthreads();
    if (tid < BM) atomicMax(&g_rmaxk[n * HWX + i0 + tid], srm[tid]);
}

// per-row sums (rowmax already computed in GEMM epilogue)
__global__ void k_row() {
    int n = blockIdx.y, i = blockIdx.x, tid = threadIdx.x;
    const uint4* row = (const uint4*)(g_cosM + ((size_t)n * HWX + i) * HWX);
    float dmp = 1.0f - funkey(g_rmaxk[n * HWX + i]) + EPSF;
    float inv = 2.0f / dmp;
    float a2  = inv * LOG2E;
    float b2  = (2.0f - inv) * LOG2E;
    float s = 0.f;
    for (int j = tid; j < HWX / 8; j += 256) {    // 8 halves per uint4
        uint4 v = row[j];
        float2 f0 = __half22float2(*(__half2*)&v.x);
        float2 f1 = __half22float2(*(__half2*)&v.y);
        float2 f2 = __half22float2(*(__half2*)&v.z);
        float2 f3 = __half22float2(*(__half2*)&v.w);
        s += fexp2(fmaf(a2, f0.x, b2)) + fexp2(fmaf(a2, f0.y, b2))
           + fexp2(fmaf(a2, f1.x, b2)) + fexp2(fmaf(a2, f1.y, b2))
           + fexp2(fmaf(a2, f2.x, b2)) + fexp2(fmaf(a2, f2.y, b2))
           + fexp2(fmaf(a2, f3.x, b2)) + fexp2(fmaf(a2, f3.y, b2));
    }
    __shared__ float red[256];
    red[tid] = s; __syncthreads();
    for (int o = 128; o > 0; o >>= 1) { if (tid < o) red[tid] += red[tid + o]; __syncthreads(); }
    if (tid == 0) {
        g_rA[n * HWX + i] = inv;
        g_rB[n * HWX + i] = (2.0f - inv) - logf(red[0]);
    }
}

// per-column: max_i (A_i*cos_ij + B_i); 2 columns per thread via half2
__global__ void __launch_bounds__(128) k_colmax() {
    int n = blockIdx.z;
    int jb = blockIdx.x * 256 + threadIdx.x * 2;
    int i0 = blockIdx.y * 128;
    __shared__ float sA[128], sB[128];
    sA[threadIdx.x] = g_rA[n * HWX + i0 + threadIdx.x];
    sB[threadIdx.x] = g_rB[n * HWX + i0 + threadIdx.x];
    __syncthreads();
    const __half2* base = (const __half2*)(g_cosM + ((size_t)n * HWX + i0) * HWX + jb);
    float bx = -1e30f, by = -1e30f;
#pragma unroll 4
    for (int ii = 0; ii < 128; ii++) {
        float2 f = __half22float2(base[(size_t)ii * (HWX / 2)]);
        bx = fmaxf(bx, fmaf(sA[ii], f.x, sB[ii]));
        by = fmaxf(by, fmaf(sA[ii], f.y, sB[ii]));
    }
    atomicMax(&g_cmax[n * HWX + jb],     fkey(bx));
    atomicMax(&g_cmax[n * HWX + jb + 1], fkey(by));
}

__global__ void k_final(float* __restrict__ out) {
    int tid = threadIdx.x;
    __shared__ float red[256];
    float acc = 0.f;
    for (int n = 0; n < Nn; n++) {
        float s = 0.f;
        for (int j = tid; j < HWX; j += 256) s += expf(funkey(g_cmax[n * HWX + j]));
        red[tid] = s; __syncthreads();
        for (int o = 128; o > 0; o >>= 1) { if (tid < o) red[tid] += red[tid + o]; __syncthreads(); }
        if (tid == 0) {
            float ccx = red[0] * (1.0f / HWX);
            acc += -logf(ccx + EPSF);
        }
        __syncthreads();
    }
    if (tid == 0) out[0] = acc * (1.0f / Nn);
}

// ---------------- launcher ----------------
extern "C" void kernel_launch(void* const* d_in, const int* in_sizes, int n_in,
                              void* d_out, int out_size) {
    const float* x = (const float*)d_in[0];
    const float* y = (const float*)d_in[1];
    float* out = (float*)d_out;

    cudaFuncSetAttribute(k_gemm, cudaFuncAttributeMaxDynamicSharedMemorySize, SMEM_DYN);

    k_init<<<(Nn * HWX + 255) / 256, 256>>>();
    k_mu<<<Cch, 256>>>(y);
    k_norm<<<dim3(HWX / 256, Nn), 256>>>(x, y);
    k_trans<<<dim3(HWX / 32, Cch / 32, Nn), dim3(32, 8)>>>(x, y);
    k_gemm<<<dim3(HWX / BN, HWX / BM, Nn), 256, SMEM_DYN>>>();
    k_row<<<dim3(HWX, Nn), 256>>>();
    k_colmax<<<dim3(HWX / 256, HWX / 128, Nn), 128>>>();
    k_final<<<1, 256>>>(out);
}

// round 13
// speedup vs baseline: 4.3802x; 1.0176x over previous
#include <cuda_runtime.h>
#include <cuda_bf16.h>
#include <cuda_fp16.h>
#include <cstdint>

#define Nn   8
#define Cch  256
#define HWX  4096
#define EPSF 1e-6f
#define LOG2E 1.44269504088896340736f

// GEMM tiling
#define BM 128
#define BN 128
#define BK 32
#define NCHUNK (Cch / BK)   // 8

// smem: row stride 80B (64B data + 16B pad) -> conflict-free ldmatrix
#define ROWB   80
#define OFF_AHI 0
#define OFF_BHI (128 * ROWB)
#define STAGE   (2 * 128 * ROWB)       // 20480
#define NSTAGE  3
#define SMEM_DYN (NSTAGE * STAGE)      // 61440

// k_prep smem (floats): sx 256*33, sy 256*33, rx 8*32, ry 8*32, sinx 32, siny 32, smu 256
#define PREP_SMEM ((256 * 33 * 2 + 8 * 32 * 2 + 32 * 2 + 256) * 4)   // 70912 B

// ---------------- device scratch ----------------
__device__ float g_mu[Cch];
__device__ __align__(16) __nv_bfloat16 g_Xhi[(size_t)Nn * HWX * Cch];  // [n][hw][c] K-major
__device__ __align__(16) __nv_bfloat16 g_Yhi[(size_t)Nn * HWX * Cch];
__device__ __align__(16) __half g_cosM[(size_t)Nn * HWX * HWX];        // 256 MB cosine (fp16)
__device__ unsigned g_rmaxk[Nn * HWX];
__device__ float g_rA[Nn * HWX];
__device__ float g_rB[Nn * HWX];
__device__ unsigned g_cmax[Nn * HWX];

// ---------------- helpers ----------------
__device__ __forceinline__ float fexp2(float x) {
    x = fmaxf(x, -80.0f);
    float fx = x + 12582912.0f;
    float r  = x - (fx - 12582912.0f);
    int   n  = __float_as_int(fx) - 0x4B400000;
    float p  = 0.69314718056f + r * (0.2402265069f + r * (0.0555041087f +
               r * (0.00961812911f + r * (0.00133335581f + r * 0.000154035304f))));
    p = 1.0f + r * p;
    return __int_as_float(__float_as_int(p) + (n << 23));
}
__device__ __forceinline__ unsigned fkey(float f) {
    unsigned u = __float_as_uint(f);
    return (u & 0x80000000u) ? ~u : (u | 0x80000000u);
}
__device__ __forceinline__ float funkey(unsigned k) {
    return __uint_as_float((k & 0x80000000u) ? (k & 0x7fffffffu) : ~k);
}
__device__ __forceinline__ uint32_t smem_u32(const void* p) {
    uint32_t a;
    asm("{ .reg .u64 t; cvta.to.shared.u64 t, %1; cvt.u32.u64 %0, t; }" : "=r"(a) : "l"(p));
    return a;
}
__device__ __forceinline__ void cpa16(uint32_t s, const void* g) {
    asm volatile("cp.async.cg.shared.global [%0], [%1], 16;\n" :: "r"(s), "l"(g));
}
__device__ __forceinline__ void ldsm4(uint32_t* r, uint32_t a) {
    asm volatile("ldmatrix.sync.aligned.m8n8.x4.shared.b16 {%0,%1,%2,%3}, [%4];"
        : "=r"(r[0]), "=r"(r[1]), "=r"(r[2]), "=r"(r[3]) : "r"(a));
}
__device__ __forceinline__ void ldsm2(uint32_t* r, uint32_t a) {
    asm volatile("ldmatrix.sync.aligned.m8n8.x2.shared.b16 {%0,%1}, [%2];"
        : "=r"(r[0]), "=r"(r[1]) : "r"(a));
}
__device__ __forceinline__ void mma16816(float* d, const uint32_t* a, const uint32_t* b) {
    asm volatile("mma.sync.aligned.m16n8k16.row.col.f32.bf16.bf16.f32 "
        "{%0,%1,%2,%3}, {%4,%5,%6,%7}, {%8,%9}, {%0,%1,%2,%3};"
        : "+f"(d[0]), "+f"(d[1]), "+f"(d[2]), "+f"(d[3])
        : "r"(a[0]), "r"(a[1]), "r"(a[2]), "r"(a[3]), "r"(b[0]), "r"(b[1]));
}

// ---------------- kernels ----------------
__global__ void k_init() {
    int idx = blockIdx.x * 256 + threadIdx.x;
    if (idx < Nn * HWX) { g_cmax[idx] = 0u; g_rmaxk[idx] = 0u; }
}

__global__ void k_mu(const float* __restrict__ y) {
    int c = blockIdx.x, tid = threadIdx.x;
    float s = 0.f;
    for (int n = 0; n < Nn; n++) {
        const float* p = y + ((size_t)n * Cch + c) * HWX;
        for (int t = tid; t < HWX; t += 256) s += p[t];
    }
    __shared__ float red[256];
    red[tid] = s; __syncthreads();
    for (int o = 128; o > 0; o >>= 1) { if (tid < o) red[tid] += red[tid + o]; __syncthreads(); }
    if (tid == 0) g_mu[c] = red[0] * (1.0f / (Nn * HWX));
}

// fused: mean-subtract + channel-norm + transpose + bf16 convert
// block: 32 pixels x 256 channels
__global__ void __launch_bounds__(256) k_prep(const float* __restrict__ x,
                                              const float* __restrict__ y) {
    extern __shared__ float dsm[];
    float* sx   = dsm;                 // [256][33]
    float* sy   = sx + 256 * 33;
    float* rx   = sy + 256 * 33;       // [8][32]
    float* ry   = rx + 8 * 32;
    float* sinx = ry + 8 * 32;         // [32]
    float* siny = sinx + 32;
    float* smu  = siny + 32;           // [256]

    int n = blockIdx.y, h0 = blockIdx.x * 32;
    int tid = threadIdx.x, lane = tid & 31, w = tid >> 5;

    smu[tid] = g_mu[tid];
    __syncthreads();

    // load: warp w handles channels w, w+8, ... ; lane = pixel
    for (int c = w; c < Cch; c += 8) {
        float m = smu[c];
        size_t off = ((size_t)n * Cch + c) * HWX + h0 + lane;
        sx[c * 33 + lane] = x[off] - m;
        sy[c * 33 + lane] = y[off] - m;
    }
    __syncthreads();

    // norm partials: warp w sums channels w+8k for pixel=lane
    float ax = 0.f, ay = 0.f;
#pragma unroll 8
    for (int k = 0; k < 32; k++) {
        int c = w + k * 8;
        float vx = sx[c * 33 + lane], vy = sy[c * 33 + lane];
        ax = fmaf(vx, vx, ax);
        ay = fmaf(vy, vy, ay);
    }
    rx[w * 32 + lane] = ax;
    ry[w * 32 + lane] = ay;
    __syncthreads();
    if (w == 0) {
        float sxs = 0.f, sys = 0.f;
#pragma unroll
        for (int g = 0; g < 8; g++) { sxs += rx[g * 32 + lane]; sys += ry[g * 32 + lane]; }
        sinx[lane] = rsqrtf(sxs);
        siny[lane] = rsqrtf(sys);
    }
    __syncthreads();

    // write transposed bf16: thread (w, lane) -> pixel=lane, channels [w*32, w*32+32)
    float inx = sinx[lane], iny = siny[lane];
    size_t ob = ((size_t)n * HWX + h0 + lane) * Cch + w * 32;
    union { __nv_bfloat16 h[8]; uint4 u; } px, py;
#pragma unroll
    for (int b = 0; b < 4; b++) {
#pragma unroll
        for (int e = 0; e < 8; e++) {
            int c = w * 32 + b * 8 + e;
            px.h[e] = __float2bfloat16(sx[c * 33 + lane] * inx);
            py.h[e] = __float2bfloat16(sy[c * 33 + lane] * iny);
        }
        *(uint4*)(g_Xhi + ob + b * 8) = px.u;
        *(uint4*)(g_Yhi + ob + b * 8) = py.u;
    }
}

// cp.async one K-chunk: A (128x32), B (128x32) bf16
__device__ __forceinline__ void load_chunk(uint32_t sbase,
        const __nv_bfloat16* Xhi, const __nv_bfloat16* Yhi,
        int i0, int j0, int k0, int tid) {
#pragma unroll
    for (int q = 0; q < 2; q++) {
        int u = tid + q * 256;
        int r = u >> 2, s = u & 3;
        uint32_t d = (uint32_t)(r * ROWB + s * 16);
        size_t goA = (size_t)(i0 + r) * Cch + k0 + s * 8;
        size_t goB = (size_t)(j0 + r) * Cch + k0 + s * 8;
        cpa16(sbase + OFF_AHI + d, Xhi + goA);
        cpa16(sbase + OFF_BHI + d, Yhi + goB);
    }
    asm volatile("cp.async.commit_group;\n" ::: "memory");
}

// HMMA GEMM: cos[n] = X * Y^T (bf16), fp16 output, fused row-max
// 3-stage pipeline, ONE sync per chunk (prefetch issued after the barrier)
__global__ void __launch_bounds__(256, 2) k_gemm() {
    extern __shared__ char smem[];
    __shared__ unsigned srm[BM];
    uint32_t sb = smem_u32(smem);
    int tid = threadIdx.x;
    int n = blockIdx.z;
    int i0 = blockIdx.y * BM, j0 = blockIdx.x * BN;

    const __nv_bfloat16* Xhi = g_Xhi + (size_t)n * HWX * Cch;
    const __nv_bfloat16* Yhi = g_Yhi + (size_t)n * HWX * Cch;

    if (tid < BM) srm[tid] = 0u;

    int w = tid >> 5, lane = tid & 31;
    int wm = w & 1, wn = w >> 1;

    uint32_t aoff = (uint32_t)((wm * 64 + (lane & 15)) * ROWB + (lane >> 4) * 16);
    uint32_t boff = (uint32_t)((wn * 32 + (lane & 7)) * ROWB + ((lane >> 3) & 1) * 16);

    float acc[4][4][4];
#pragma unroll
    for (int a = 0; a < 4; a++)
#pragma unroll
        for (int b = 0; b < 4; b++)
#pragma unroll
            for (int c = 0; c < 4; c++) acc[a][b][c] = 0.f;

    load_chunk(sb,         Xhi, Yhi, i0, j0, 0,  tid);
    load_chunk(sb + STAGE, Xhi, Yhi, i0, j0, BK, tid);

    for (int c = 0; c < NCHUNK; c++) {
        uint32_t scur = sb + (uint32_t)(c % NSTAGE) * STAGE;
        if (c + 1 < NCHUNK) {
            asm volatile("cp.async.wait_group 1;\n" ::: "memory");
        } else {
            asm volatile("cp.async.wait_group 0;\n" ::: "memory");
        }
        __syncthreads();   // all warps done with chunk c-1 -> safe to refill its stage
        if (c + 2 < NCHUNK)
            load_chunk(sb + (uint32_t)((c + 2) % NSTAGE) * STAGE,
                       Xhi, Yhi, i0, j0, (c + 2) * BK, tid);

#pragma unroll
        for (int k16 = 0; k16 < 2; k16++) {
            uint32_t ka = scur + aoff + k16 * 32;
            uint32_t kb = scur + boff + k16 * 32;
            uint32_t ahi[4][4], bhi[4][2];
#pragma unroll
            for (int mi = 0; mi < 4; mi++)
                ldsm4(ahi[mi], ka + OFF_AHI + mi * 16 * ROWB);
#pragma unroll
            for (int ni = 0; ni < 4; ni++)
                ldsm2(bhi[ni], kb + OFF_BHI + ni * 8 * ROWB);
#pragma unroll
            for (int mi = 0; mi < 4; mi++)
#pragma unroll
                for (int ni = 0; ni < 4; ni++)
                    mma16816(acc[mi][ni], ahi[mi], bhi[ni]);
        }
    }

    // epilogue: fp16 store + fused row-max over the ROUNDED values
    int rl0 = wm * 64 + (lane >> 2);
    int cb  = j0 + wn * 32 + 2 * (lane & 3);
#pragma unroll
    for (int mi = 0; mi < 4; mi++) {
        int r1 = rl0 + mi * 16, r2 = r1 + 8;
        float m1 = -1e30f, m2 = -1e30f;
        __half* p1 = g_cosM + ((size_t)n * HWX + i0 + r1) * HWX + cb;
        __half* p2 = g_cosM + ((size_t)n * HWX + i0 + r2) * HWX + cb;
#pragma unroll
        for (int ni = 0; ni < 4; ni++) {
            __half2 h1 = __floats2half2_rn(acc[mi][ni][0], acc[mi][ni][1]);
            __half2 h2 = __floats2half2_rn(acc[mi][ni][2], acc[mi][ni][3]);
            float2 f1 = __half22float2(h1);
            float2 f2 = __half22float2(h2);
            m1 = fmaxf(m1, fmaxf(f1.x, f1.y));
            m2 = fmaxf(m2, fmaxf(f2.x, f2.y));
            *(__half2*)(p1 + ni * 8) = h1;
            *(__half2*)(p2 + ni * 8) = h2;
        }
        atomicMax(&srm[r1], fkey(m1));
        atomicMax(&srm[r2], fkey(m2));
    }
    __syncthreads();
    if (tid < BM) atomicMax(&g_rmaxk[n * HWX + i0 + tid], srm[tid]);
}

// per-row sums (rowmax already computed in GEMM epilogue)
__global__ void k_row() {
    int n = blockIdx.y, i = blockIdx.x, tid = threadIdx.x;
    const uint4* row = (const uint4*)(g_cosM + ((size_t)n * HWX + i) * HWX);
    float dmp = 1.0f - funkey(g_rmaxk[n * HWX + i]) + EPSF;
    float inv = 2.0f / dmp;
    float a2  = inv * LOG2E;
    float b2  = (2.0f - inv) * LOG2E;
    float s = 0.f;
#pragma unroll
    for (int j = tid; j < HWX / 8; j += 256) {
        uint4 v = row[j];
        float2 f0 = __half22float2(*(__half2*)&v.x);
        float2 f1 = __half22float2(*(__half2*)&v.y);
        float2 f2 = __half22float2(*(__half2*)&v.z);
        float2 f3 = __half22float2(*(__half2*)&v.w);
        s += fexp2(fmaf(a2, f0.x, b2)) + fexp2(fmaf(a2, f0.y, b2))
           + fexp2(fmaf(a2, f1.x, b2)) + fexp2(fmaf(a2, f1.y, b2))
           + fexp2(fmaf(a2, f2.x, b2)) + fexp2(fmaf(a2, f2.y, b2))
           + fexp2(fmaf(a2, f3.x, b2)) + fexp2(fmaf(a2, f3.y, b2));
    }
    __shared__ float red[256];
    red[tid] = s; __syncthreads();
    for (int o = 128; o > 0; o >>= 1) { if (tid < o) red[tid] += red[tid + o]; __syncthreads(); }
    if (tid == 0) {
        g_rA[n * HWX + i] = inv;
        g_rB[n * HWX + i] = (2.0f - inv) - logf(red[0]);
    }
}

// per-column: max_i (A_i*cos_ij + B_i); 8 columns per thread via uint4 loads
__global__ void __launch_bounds__(128) k_colmax() {
    int n = blockIdx.z;
    int jb = blockIdx.x * 1024 + threadIdx.x * 8;
    int i0 = blockIdx.y * 128;
    __shared__ float sA[128], sB[128];
    sA[threadIdx.x] = g_rA[n * HWX + i0 + threadIdx.x];
    sB[threadIdx.x] = g_rB[n * HWX + i0 + threadIdx.x];
    __syncthreads();
    const uint4* base = (const uint4*)(g_cosM + ((size_t)n * HWX + i0) * HWX + jb);
    float m[8];
#pragma unroll
    for (int e = 0; e < 8; e++) m[e] = -1e30f;
#pragma unroll 4
    for (int ii = 0; ii < 128; ii++) {
        uint4 v = base[(size_t)ii * (HWX / 8)];
        float a = sA[ii], b = sB[ii];
        float2 f0 = __half22float2(*(__half2*)&v.x);
        float2 f1 = __half22float2(*(__half2*)&v.y);
        float2 f2 = __half22float2(*(__half2*)&v.z);
        float2 f3 = __half22float2(*(__half2*)&v.w);
        m[0] = fmaxf(m[0], fmaf(a, f0.x, b));
        m[1] = fmaxf(m[1], fmaf(a, f0.y, b));
        m[2] = fmaxf(m[2], fmaf(a, f1.x, b));
        m[3] = fmaxf(m[3], fmaf(a, f1.y, b));
        m[4] = fmaxf(m[4], fmaf(a, f2.x, b));
        m[5] = fmaxf(m[5], fmaf(a, f2.y, b));
        m[6] = fmaxf(m[6], fmaf(a, f3.x, b));
        m[7] = fmaxf(m[7], fmaf(a, f3.y, b));
    }
#pragma unroll
    for (int e = 0; e < 8; e++)
        atomicMax(&g_cmax[n * HWX + jb + e], fkey(m[e]));
}

__global__ void k_final(float* __restrict__ out) {
    int tid = threadIdx.x;
    __shared__ float red[256];
    float acc = 0.f;
    for (int n = 0; n < Nn; n++) {
        float s = 0.f;
        for (int j = tid; j < HWX; j += 256) s += expf(funkey(g_cmax[n * HWX + j]));
        red[tid] = s; __syncthreads();
        for (int o = 128; o > 0; o >>= 1) { if (tid < o) red[tid] += red[tid + o]; __syncthreads(); }
        if (tid == 0) {
            float ccx = red[0] * (1.0f / HWX);
            acc += -logf(ccx + EPSF);
        }
        __syncthreads();
    }
    if (tid == 0) out[0] = acc * (1.0f / Nn);
}

// ---------------- launcher ----------------
extern "C" void kernel_launch(void* const* d_in, const int* in_sizes, int n_in,
                              void* d_out, int out_size) {
    const float* x = (const float*)d_in[0];
    const float* y = (const float*)d_in[1];
    float* out = (float*)d_out;

    cudaFuncSetAttribute(k_gemm, cudaFuncAttributeMaxDynamicSharedMemorySize, SMEM_DYN);
    cudaFuncSetAttribute(k_prep, cudaFuncAttributeMaxDynamicSharedMemorySize, PREP_SMEM);

    k_init<<<(Nn * HWX + 255) / 256, 256>>>();
    k_mu<<<Cch, 256>>>(y);
    k_prep<<<dim3(HWX / 32, Nn), 256, PREP_SMEM>>>(x, y);
    k_gemm<<<dim3(HWX / BN, HWX / BM, Nn), 256, SMEM_DYN>>>();
    k_row<<<dim3(HWX, Nn), 256>>>();
    k_colmax<<<dim3(HWX / 1024, HWX / 128, Nn), 128>>>();
    k_final<<<1, 256>>>(out);
}